// round 14
// baseline (speedup 1.0000x reference)
#include <cuda_runtime.h>
#include <cstdint>

// Problem constants (fixed shapes from reference)
#define BB   2
#define HH   384
#define WW   1216
#define HWSZ (HH * WW)            // 466944
#define NPIX (BB * HWSZ)          // 933888
#define NB   256

#define THREADS1   128
#define PIX_PER_T  16
#define NBLK1      (NPIX / (THREADS1 * PIX_PER_T))   // 456 exactly, no tail

// Fixed-slot scratch for deterministic reduction: 3 planes of 512 slots
__device__ float g_part[3 * 512];
__device__ unsigned int g_count = 0;   // wraps mod NBLK1 -> self-resetting per launch

__device__ __forceinline__ float warp_sum_f(float v) {
    #pragma unroll
    for (int o = 16; o > 0; o >>= 1) v += __shfl_down_sync(0xffffffffu, v, o);
    return v;
}
__device__ __forceinline__ double warp_sum_d(double v) {
    #pragma unroll
    for (int o = 16; o > 0; o >>= 1) v += __shfl_down_sync(0xffffffffu, v, o);
    return v;
}

__global__ void __launch_bounds__(THREADS1)
disp_loss_fused(const float* __restrict__ coord,
                const float* __restrict__ logits,
                const float* __restrict__ disp,
                const int* __restrict__ valid,   // jnp bool materialized as int32
                float* __restrict__ out, int out_size)
{
    const int t = blockIdx.x * THREADS1 + threadIdx.x;
    const int p = t * PIX_PER_T;                  // base pixel (aligned 16; W % 16 == 0)

    const int b  = p / HWSZ;
    const int r  = p - b * HWSZ;
    const int h  = r / WW;
    const int w0 = r - h * WW;

    // base of (b, c=0, h, w0) in the (B,256,H,W) logits tensor
    const float* base = logits + (size_t)b * NB * HWSZ + (size_t)h * WW + w0;

    // ---- streaming sum of exp over 256 channels (16 pixels per thread) ----
    // Four contiguous LDG.128 per iter (same base reg, +16/+32/+48B imm) -> high MLP.
    // Grid 456 blocks, whole grid resident (3 blocks/SM).
    float s[PIX_PER_T];
    #pragma unroll
    for (int j = 0; j < PIX_PER_T; ++j) s[j] = 0.f;

    const float4* ptr = reinterpret_cast<const float4*>(base);
    #pragma unroll 8
    for (int c = 0; c < NB; ++c) {
        const float4 va = __ldcs(ptr);
        const float4 vb = __ldcs(ptr + 1);
        const float4 vc = __ldcs(ptr + 2);
        const float4 vd = __ldcs(ptr + 3);
        ptr += (HWSZ / 4);
        s[0]  += __expf(va.x);  s[1]  += __expf(va.y);
        s[2]  += __expf(va.z);  s[3]  += __expf(va.w);
        s[4]  += __expf(vb.x);  s[5]  += __expf(vb.y);
        s[6]  += __expf(vb.z);  s[7]  += __expf(vb.w);
        s[8]  += __expf(vc.x);  s[9]  += __expf(vc.y);
        s[10] += __expf(vc.z);  s[11] += __expf(vc.w);
        s[12] += __expf(vd.x);  s[13] += __expf(vd.y);
        s[14] += __expf(vd.z);  s[15] += __expf(vd.w);
    }

    float dd[PIX_PER_T], cc[PIX_PER_T];
    int   vv[PIX_PER_T];
    #pragma unroll
    for (int q = 0; q < PIX_PER_T / 4; ++q) {
        const float4 d4 = *reinterpret_cast<const float4*>(disp  + p + 4 * q);
        const float4 c4 = *reinterpret_cast<const float4*>(coord + p + 4 * q);
        const int4   v4 = *reinterpret_cast<const int4*>(valid   + p + 4 * q);
        dd[4*q+0] = d4.x; dd[4*q+1] = d4.y; dd[4*q+2] = d4.z; dd[4*q+3] = d4.w;
        cc[4*q+0] = c4.x; cc[4*q+1] = c4.y; cc[4*q+2] = c4.z; cc[4*q+3] = c4.w;
        vv[4*q+0] = v4.x; vv[4*q+1] = v4.y; vv[4*q+2] = v4.z; vv[4*q+3] = v4.w;
    }

    const float SHIFT    = 0.1f * (float)WW;          // 121.6
    const float LAB_MAX  = 1.1f * (float)WW;          // 1337.6
    const float INV_INTV = 255.0f / (1.1f * (float)WW);

    float msum = 0.f, csum = 0.f, cesum = 0.f;
    #pragma unroll
    for (int j = 0; j < PIX_PER_T; ++j) {
        const float dv     = dd[j];
        const float m      = (vv[j] != 0 && dv < 192.0f) ? 1.0f : 0.0f;
        const float target = (float)(w0 + j) - dv;

        const float labels = fminf(fmaxf(target + SHIFT, 0.0f), LAB_MAX);
        const float pos    = labels * INV_INTV;        // in [0,255]
        const int   lb     = (int)floorf(pos);
        const int   hb     = min(lb + 1, NB - 1);
        const float wh     = pos - (float)lb;

        const float xlb = __ldg(base + (size_t)lb * HWSZ + j);
        const float xhb = __ldg(base + (size_t)hb * HWSZ + j);
        const float lse = __logf(s[j]);
        const float ce  = lse - ((1.0f - wh) * xlb + wh * xhb);

        msum  += m;
        csum  += fabsf(cc[j] - target) * m;
        cesum += ce * m;
    }

    // ---- deterministic block reduction ----
    __shared__ float sh[3][THREADS1 / 32];
    const int lane = threadIdx.x & 31;
    const int wid  = threadIdx.x >> 5;

    msum  = warp_sum_f(msum);
    csum  = warp_sum_f(csum);
    cesum = warp_sum_f(cesum);
    if (lane == 0) { sh[0][wid] = msum; sh[1][wid] = csum; sh[2][wid] = cesum; }
    __syncthreads();

    __shared__ bool s_last;
    if (threadIdx.x == 0) {
        const int nw = THREADS1 / 32;
        float a = 0.f, bs = 0.f, c2 = 0.f;
        #pragma unroll
        for (int i = 0; i < nw; ++i) { a += sh[0][i]; bs += sh[1][i]; c2 += sh[2][i]; }
        g_part[blockIdx.x]        = a;
        g_part[512  + blockIdx.x] = bs;
        g_part[1024 + blockIdx.x] = c2;
        __threadfence();
        const unsigned old = atomicInc(&g_count, NBLK1 - 1);  // wraps to 0 on last
        s_last = (old == NBLK1 - 1);
    }
    __syncthreads();

    // ---- last block: final reduction in double (fixed order => deterministic) ----
    if (s_last) {
        __threadfence();
        double a = 0.0, bs = 0.0, c2 = 0.0;
        for (int i = threadIdx.x; i < NBLK1; i += THREADS1) {
            a  += (double)__ldcg(&g_part[i]);
            bs += (double)__ldcg(&g_part[512  + i]);
            c2 += (double)__ldcg(&g_part[1024 + i]);
        }
        __shared__ double dsh[3][THREADS1 / 32];
        a  = warp_sum_d(a);
        bs = warp_sum_d(bs);
        c2 = warp_sum_d(c2);
        if (lane == 0) { dsh[0][wid] = a; dsh[1][wid] = bs; dsh[2][wid] = c2; }
        __syncthreads();
        if (threadIdx.x == 0) {
            const int nw = THREADS1 / 32;
            double A = 0.0, Bs = 0.0, C = 0.0;
            #pragma unroll
            for (int i = 0; i < nw; ++i) { A += dsh[0][i]; Bs += dsh[1][i]; C += dsh[2][i]; }
            const double denom       = A + 1e-6;
            const double coord_loss  = Bs / denom;
            const double logits_loss = C / denom;
            out[0] = (float)(0.1 * coord_loss + logits_loss);
            if (out_size >= 3) {
                out[1] = (float)coord_loss;
                out[2] = (float)logits_loss;
            }
        }
    }
}

extern "C" void kernel_launch(void* const* d_in, const int* in_sizes, int n_in,
                              void* d_out, int out_size)
{
    const float* coord  = (const float*)d_in[0];
    const float* logits = (const float*)d_in[1];
    const float* disp   = (const float*)d_in[2];
    const int*   valid  = (const int*)d_in[3];
    float* out = (float*)d_out;

    disp_loss_fused<<<NBLK1, THREADS1>>>(coord, logits, disp, valid, out, out_size);
}

// round 15
// speedup vs baseline: 1.2587x; 1.2587x over previous
#include <cuda_runtime.h>
#include <cstdint>

// Problem constants (fixed shapes from reference)
#define BB   2
#define HH   384
#define WW   1216
#define HWSZ (HH * WW)            // 466944
#define NPIX (BB * HWSZ)          // 933888
#define NB   256

#define THREADS1   128
#define PIX_PER_T  8
#define NBLK1      (NPIX / (THREADS1 * PIX_PER_T))   // 912 exactly, no tail

// Fixed-slot scratch for deterministic reduction: 3 planes of 1024 slots
__device__ float g_part[3 * 1024];
__device__ unsigned int g_count = 0;   // wraps mod NBLK1 -> self-resetting per launch

__device__ __forceinline__ float warp_sum_f(float v) {
    #pragma unroll
    for (int o = 16; o > 0; o >>= 1) v += __shfl_down_sync(0xffffffffu, v, o);
    return v;
}
__device__ __forceinline__ double warp_sum_d(double v) {
    #pragma unroll
    for (int o = 16; o > 0; o >>= 1) v += __shfl_down_sync(0xffffffffu, v, o);
    return v;
}

__global__ void __launch_bounds__(THREADS1)
disp_loss_fused(const float* __restrict__ coord,
                const float* __restrict__ logits,
                const float* __restrict__ disp,
                const int* __restrict__ valid,   // jnp bool materialized as int32
                float* __restrict__ out, int out_size)
{
    const int t = blockIdx.x * THREADS1 + threadIdx.x;
    const int p = t * PIX_PER_T;                  // base pixel (aligned 8; W % 8 == 0)

    const int b  = p / HWSZ;
    const int r  = p - b * HWSZ;
    const int h  = r / WW;
    const int w0 = r - h * WW;

    // base of (b, c=0, h, w0) in the (B,256,H,W) logits tensor
    const float* base = logits + (size_t)b * NB * HWSZ + (size_t)h * WW + w0;

    // ---- streaming sum of exp over 256 channels (8 pixels per thread) ----
    // Two contiguous LDG.128 per iter (same base reg, +16B imm); unroll 16 ->
    // up to 32 front-batched loads per window. Whole grid resident in one wave.
    float s0 = 0.f, s1 = 0.f, s2 = 0.f, s3 = 0.f;
    float s4 = 0.f, s5 = 0.f, s6 = 0.f, s7 = 0.f;
    const float4* ptr = reinterpret_cast<const float4*>(base);
    #pragma unroll 16
    for (int c = 0; c < NB; ++c) {
        const float4 va = __ldcs(ptr);
        const float4 vb = __ldcs(ptr + 1);
        ptr += (HWSZ / 4);
        s0 += __expf(va.x);
        s1 += __expf(va.y);
        s2 += __expf(va.z);
        s3 += __expf(va.w);
        s4 += __expf(vb.x);
        s5 += __expf(vb.y);
        s6 += __expf(vb.z);
        s7 += __expf(vb.w);
    }
    const float ss[8] = {s0, s1, s2, s3, s4, s5, s6, s7};

    const float4 dA = *reinterpret_cast<const float4*>(disp + p);
    const float4 dB = *reinterpret_cast<const float4*>(disp + p + 4);
    const float4 cA = *reinterpret_cast<const float4*>(coord + p);
    const float4 cB = *reinterpret_cast<const float4*>(coord + p + 4);
    const int4   vA = *reinterpret_cast<const int4*>(valid + p);
    const int4   vB = *reinterpret_cast<const int4*>(valid + p + 4);

    const float dd[8] = {dA.x, dA.y, dA.z, dA.w, dB.x, dB.y, dB.z, dB.w};
    const float cc[8] = {cA.x, cA.y, cA.z, cA.w, cB.x, cB.y, cB.z, cB.w};
    const int   vv[8] = {vA.x, vA.y, vA.z, vA.w, vB.x, vB.y, vB.z, vB.w};

    const float SHIFT    = 0.1f * (float)WW;          // 121.6
    const float LAB_MAX  = 1.1f * (float)WW;          // 1337.6
    const float INV_INTV = 255.0f / (1.1f * (float)WW);

    float msum = 0.f, csum = 0.f, cesum = 0.f;
    #pragma unroll
    for (int j = 0; j < PIX_PER_T; ++j) {
        const float dv     = dd[j];
        const float m      = (vv[j] != 0 && dv < 192.0f) ? 1.0f : 0.0f;
        const float target = (float)(w0 + j) - dv;

        const float labels = fminf(fmaxf(target + SHIFT, 0.0f), LAB_MAX);
        const float pos    = labels * INV_INTV;        // in [0,255]
        const int   lb     = (int)floorf(pos);
        const int   hb     = min(lb + 1, NB - 1);
        const float wh     = pos - (float)lb;

        const float xlb = __ldg(base + (size_t)lb * HWSZ + j);
        const float xhb = __ldg(base + (size_t)hb * HWSZ + j);
        const float lse = __logf(ss[j]);
        const float ce  = lse - ((1.0f - wh) * xlb + wh * xhb);

        msum  += m;
        csum  += fabsf(cc[j] - target) * m;
        cesum += ce * m;
    }

    // ---- deterministic block reduction ----
    __shared__ float sh[3][THREADS1 / 32];
    const int lane = threadIdx.x & 31;
    const int wid  = threadIdx.x >> 5;

    msum  = warp_sum_f(msum);
    csum  = warp_sum_f(csum);
    cesum = warp_sum_f(cesum);
    if (lane == 0) { sh[0][wid] = msum; sh[1][wid] = csum; sh[2][wid] = cesum; }
    __syncthreads();

    __shared__ bool s_last;
    if (threadIdx.x == 0) {
        const int nw = THREADS1 / 32;
        float a = 0.f, bs = 0.f, c2 = 0.f;
        #pragma unroll
        for (int i = 0; i < nw; ++i) { a += sh[0][i]; bs += sh[1][i]; c2 += sh[2][i]; }
        g_part[blockIdx.x]        = a;
        g_part[1024 + blockIdx.x] = bs;
        g_part[2048 + blockIdx.x] = c2;
        __threadfence();
        const unsigned old = atomicInc(&g_count, NBLK1 - 1);  // wraps to 0 on last
        s_last = (old == NBLK1 - 1);
    }
    __syncthreads();

    // ---- last block: final reduction in double (fixed order => deterministic) ----
    if (s_last) {
        __threadfence();
        double a = 0.0, bs = 0.0, c2 = 0.0;
        for (int i = threadIdx.x; i < NBLK1; i += THREADS1) {
            a  += (double)__ldcg(&g_part[i]);
            bs += (double)__ldcg(&g_part[1024 + i]);
            c2 += (double)__ldcg(&g_part[2048 + i]);
        }
        __shared__ double dsh[3][THREADS1 / 32];
        a  = warp_sum_d(a);
        bs = warp_sum_d(bs);
        c2 = warp_sum_d(c2);
        if (lane == 0) { dsh[0][wid] = a; dsh[1][wid] = bs; dsh[2][wid] = c2; }
        __syncthreads();
        if (threadIdx.x == 0) {
            const int nw = THREADS1 / 32;
            double A = 0.0, Bs = 0.0, C = 0.0;
            #pragma unroll
            for (int i = 0; i < nw; ++i) { A += dsh[0][i]; Bs += dsh[1][i]; C += dsh[2][i]; }
            const double denom       = A + 1e-6;
            const double coord_loss  = Bs / denom;
            const double logits_loss = C / denom;
            out[0] = (float)(0.1 * coord_loss + logits_loss);
            if (out_size >= 3) {
                out[1] = (float)coord_loss;
                out[2] = (float)logits_loss;
            }
        }
    }
}

extern "C" void kernel_launch(void* const* d_in, const int* in_sizes, int n_in,
                              void* d_out, int out_size)
{
    const float* coord  = (const float*)d_in[0];
    const float* logits = (const float*)d_in[1];
    const float* disp   = (const float*)d_in[2];
    const int*   valid  = (const int*)d_in[3];
    float* out = (float*)d_out;

    disp_loss_fused<<<NBLK1, THREADS1>>>(coord, logits, disp, valid, out, out_size);
}

// round 16
// speedup vs baseline: 1.2713x; 1.0100x over previous
#include <cuda_runtime.h>
#include <cstdint>

// Problem constants (fixed shapes from reference)
#define BB   2
#define HH   384
#define WW   1216
#define HWSZ (HH * WW)            // 466944
#define NPIX (BB * HWSZ)          // 933888
#define NB   256

#define THREADS1   128
#define PIX_PER_T  8
#define NBLK1      (NPIX / (THREADS1 * PIX_PER_T))   // 912 exactly, no tail

// Fixed-slot scratch for deterministic reduction: 3 planes of 1024 slots
__device__ float g_part[3 * 1024];
__device__ unsigned int g_count = 0;   // wraps mod NBLK1 -> self-resetting per launch

__device__ __forceinline__ float warp_sum_f(float v) {
    #pragma unroll
    for (int o = 16; o > 0; o >>= 1) v += __shfl_down_sync(0xffffffffu, v, o);
    return v;
}
__device__ __forceinline__ double warp_sum_d(double v) {
    #pragma unroll
    for (int o = 16; o > 0; o >>= 1) v += __shfl_down_sync(0xffffffffu, v, o);
    return v;
}

__global__ void __launch_bounds__(THREADS1)
disp_loss_fused(const float* __restrict__ coord,
                const float* __restrict__ logits,
                const float* __restrict__ disp,
                const int* __restrict__ valid,   // jnp bool materialized as int32
                float* __restrict__ out, int out_size)
{
    const int t = blockIdx.x * THREADS1 + threadIdx.x;
    const int p = t * PIX_PER_T;                  // base pixel (aligned 8; W % 8 == 0)

    const int b  = p / HWSZ;
    const int r  = p - b * HWSZ;
    const int h  = r / WW;
    const int w0 = r - h * WW;

    // base of (b, c=0, h, w0) in the (B,256,H,W) logits tensor
    const float* base = logits + (size_t)b * NB * HWSZ + (size_t)h * WW + w0;

    // ---- streaming sum of exp over 256 channels (8 pixels per thread) ----
    // Two contiguous LDG.128 per iter (same base reg, +16B imm); unroll 32 ->
    // up to 64 front-batched loads per window. Whole grid resident in one wave.
    float s0 = 0.f, s1 = 0.f, s2 = 0.f, s3 = 0.f;
    float s4 = 0.f, s5 = 0.f, s6 = 0.f, s7 = 0.f;
    const float4* ptr = reinterpret_cast<const float4*>(base);
    #pragma unroll 32
    for (int c = 0; c < NB; ++c) {
        const float4 va = __ldcs(ptr);
        const float4 vb = __ldcs(ptr + 1);
        ptr += (HWSZ / 4);
        s0 += __expf(va.x);
        s1 += __expf(va.y);
        s2 += __expf(va.z);
        s3 += __expf(va.w);
        s4 += __expf(vb.x);
        s5 += __expf(vb.y);
        s6 += __expf(vb.z);
        s7 += __expf(vb.w);
    }
    const float ss[8] = {s0, s1, s2, s3, s4, s5, s6, s7};

    const float4 dA = *reinterpret_cast<const float4*>(disp + p);
    const float4 dB = *reinterpret_cast<const float4*>(disp + p + 4);
    const float4 cA = *reinterpret_cast<const float4*>(coord + p);
    const float4 cB = *reinterpret_cast<const float4*>(coord + p + 4);
    const int4   vA = *reinterpret_cast<const int4*>(valid + p);
    const int4   vB = *reinterpret_cast<const int4*>(valid + p + 4);

    const float dd[8] = {dA.x, dA.y, dA.z, dA.w, dB.x, dB.y, dB.z, dB.w};
    const float cc[8] = {cA.x, cA.y, cA.z, cA.w, cB.x, cB.y, cB.z, cB.w};
    const int   vv[8] = {vA.x, vA.y, vA.z, vA.w, vB.x, vB.y, vB.z, vB.w};

    const float SHIFT    = 0.1f * (float)WW;          // 121.6
    const float LAB_MAX  = 1.1f * (float)WW;          // 1337.6
    const float INV_INTV = 255.0f / (1.1f * (float)WW);

    float msum = 0.f, csum = 0.f, cesum = 0.f;
    #pragma unroll
    for (int j = 0; j < PIX_PER_T; ++j) {
        const float dv     = dd[j];
        const float m      = (vv[j] != 0 && dv < 192.0f) ? 1.0f : 0.0f;
        const float target = (float)(w0 + j) - dv;

        const float labels = fminf(fmaxf(target + SHIFT, 0.0f), LAB_MAX);
        const float pos    = labels * INV_INTV;        // in [0,255]
        const int   lb     = (int)floorf(pos);
        const int   hb     = min(lb + 1, NB - 1);
        const float wh     = pos - (float)lb;

        const float xlb = __ldg(base + (size_t)lb * HWSZ + j);
        const float xhb = __ldg(base + (size_t)hb * HWSZ + j);
        const float lse = __logf(ss[j]);
        const float ce  = lse - ((1.0f - wh) * xlb + wh * xhb);

        msum  += m;
        csum  += fabsf(cc[j] - target) * m;
        cesum += ce * m;
    }

    // ---- deterministic block reduction ----
    __shared__ float sh[3][THREADS1 / 32];
    const int lane = threadIdx.x & 31;
    const int wid  = threadIdx.x >> 5;

    msum  = warp_sum_f(msum);
    csum  = warp_sum_f(csum);
    cesum = warp_sum_f(cesum);
    if (lane == 0) { sh[0][wid] = msum; sh[1][wid] = csum; sh[2][wid] = cesum; }
    __syncthreads();

    __shared__ bool s_last;
    if (threadIdx.x == 0) {
        const int nw = THREADS1 / 32;
        float a = 0.f, bs = 0.f, c2 = 0.f;
        #pragma unroll
        for (int i = 0; i < nw; ++i) { a += sh[0][i]; bs += sh[1][i]; c2 += sh[2][i]; }
        g_part[blockIdx.x]        = a;
        g_part[1024 + blockIdx.x] = bs;
        g_part[2048 + blockIdx.x] = c2;
        __threadfence();
        const unsigned old = atomicInc(&g_count, NBLK1 - 1);  // wraps to 0 on last
        s_last = (old == NBLK1 - 1);
    }
    __syncthreads();

    // ---- last block: final reduction in double (fixed order => deterministic) ----
    if (s_last) {
        __threadfence();
        double a = 0.0, bs = 0.0, c2 = 0.0;
        for (int i = threadIdx.x; i < NBLK1; i += THREADS1) {
            a  += (double)__ldcg(&g_part[i]);
            bs += (double)__ldcg(&g_part[1024 + i]);
            c2 += (double)__ldcg(&g_part[2048 + i]);
        }
        __shared__ double dsh[3][THREADS1 / 32];
        a  = warp_sum_d(a);
        bs = warp_sum_d(bs);
        c2 = warp_sum_d(c2);
        if (lane == 0) { dsh[0][wid] = a; dsh[1][wid] = bs; dsh[2][wid] = c2; }
        __syncthreads();
        if (threadIdx.x == 0) {
            const int nw = THREADS1 / 32;
            double A = 0.0, Bs = 0.0, C = 0.0;
            #pragma unroll
            for (int i = 0; i < nw; ++i) { A += dsh[0][i]; Bs += dsh[1][i]; C += dsh[2][i]; }
            const double denom       = A + 1e-6;
            const double coord_loss  = Bs / denom;
            const double logits_loss = C / denom;
            out[0] = (float)(0.1 * coord_loss + logits_loss);
            if (out_size >= 3) {
                out[1] = (float)coord_loss;
                out[2] = (float)logits_loss;
            }
        }
    }
}

extern "C" void kernel_launch(void* const* d_in, const int* in_sizes, int n_in,
                              void* d_out, int out_size)
{
    const float* coord  = (const float*)d_in[0];
    const float* logits = (const float*)d_in[1];
    const float* disp   = (const float*)d_in[2];
    const int*   valid  = (const int*)d_in[3];
    float* out = (float*)d_out;

    disp_loss_fused<<<NBLK1, THREADS1>>>(coord, logits, disp, valid, out, out_size);
}

// round 17
// speedup vs baseline: 1.2872x; 1.0125x over previous
#include <cuda_runtime.h>
#include <cstdint>

// Problem constants (fixed shapes from reference)
#define BB   2
#define HH   384
#define WW   1216
#define HWSZ (HH * WW)            // 466944
#define NPIX (BB * HWSZ)          // 933888
#define NB   256

#define THREADS1   128
#define PIX_PER_T  8
#define NBLK1      (NPIX / (THREADS1 * PIX_PER_T))   // 912 exactly, no tail

// Fixed-slot scratch for deterministic reduction: 3 planes of 1024 slots
__device__ float g_part[3 * 1024];
__device__ unsigned int g_count = 0;   // wraps mod NBLK1 -> self-resetting per launch

__device__ __forceinline__ float warp_sum_f(float v) {
    #pragma unroll
    for (int o = 16; o > 0; o >>= 1) v += __shfl_down_sync(0xffffffffu, v, o);
    return v;
}
__device__ __forceinline__ double warp_sum_d(double v) {
    #pragma unroll
    for (int o = 16; o > 0; o >>= 1) v += __shfl_down_sync(0xffffffffu, v, o);
    return v;
}

__global__ void __launch_bounds__(THREADS1)
disp_loss_fused(const float* __restrict__ coord,
                const float* __restrict__ logits,
                const float* __restrict__ disp,
                const int* __restrict__ valid,   // jnp bool materialized as int32
                float* __restrict__ out, int out_size)
{
    const int t = blockIdx.x * THREADS1 + threadIdx.x;
    const int p = t * PIX_PER_T;                  // base pixel (aligned 8; W % 8 == 0)

    const int b  = p / HWSZ;
    const int r  = p - b * HWSZ;
    const int h  = r / WW;
    const int w0 = r - h * WW;

    // base of (b, c=0, h, w0) in the (B,256,H,W) logits tensor
    const float* base = logits + (size_t)b * NB * HWSZ + (size_t)h * WW + w0;

    // ---- streaming sum of exp over 256 channels (8 pixels per thread) ----
    // Two contiguous LDG.128 per iter (same base reg, +16B imm); unroll 16 ->
    // up to 32 front-batched loads per window. Whole grid resident in one wave.
    float s0 = 0.f, s1 = 0.f, s2 = 0.f, s3 = 0.f;
    float s4 = 0.f, s5 = 0.f, s6 = 0.f, s7 = 0.f;
    const float4* ptr = reinterpret_cast<const float4*>(base);
    #pragma unroll 16
    for (int c = 0; c < NB; ++c) {
        const float4 va = __ldcs(ptr);
        const float4 vb = __ldcs(ptr + 1);
        ptr += (HWSZ / 4);
        s0 += __expf(va.x);
        s1 += __expf(va.y);
        s2 += __expf(va.z);
        s3 += __expf(va.w);
        s4 += __expf(vb.x);
        s5 += __expf(vb.y);
        s6 += __expf(vb.z);
        s7 += __expf(vb.w);
    }
    const float ss[8] = {s0, s1, s2, s3, s4, s5, s6, s7};

    const float4 dA = *reinterpret_cast<const float4*>(disp + p);
    const float4 dB = *reinterpret_cast<const float4*>(disp + p + 4);
    const float4 cA = *reinterpret_cast<const float4*>(coord + p);
    const float4 cB = *reinterpret_cast<const float4*>(coord + p + 4);
    const int4   vA = *reinterpret_cast<const int4*>(valid + p);
    const int4   vB = *reinterpret_cast<const int4*>(valid + p + 4);

    const float dd[8] = {dA.x, dA.y, dA.z, dA.w, dB.x, dB.y, dB.z, dB.w};
    const float cc[8] = {cA.x, cA.y, cA.z, cA.w, cB.x, cB.y, cB.z, cB.w};
    const int   vv[8] = {vA.x, vA.y, vA.z, vA.w, vB.x, vB.y, vB.z, vB.w};

    const float SHIFT    = 0.1f * (float)WW;          // 121.6
    const float LAB_MAX  = 1.1f * (float)WW;          // 1337.6
    const float INV_INTV = 255.0f / (1.1f * (float)WW);

    float msum = 0.f, csum = 0.f, cesum = 0.f;
    #pragma unroll
    for (int j = 0; j < PIX_PER_T; ++j) {
        const float dv     = dd[j];
        const float m      = (vv[j] != 0 && dv < 192.0f) ? 1.0f : 0.0f;
        const float target = (float)(w0 + j) - dv;

        const float labels = fminf(fmaxf(target + SHIFT, 0.0f), LAB_MAX);
        const float pos    = labels * INV_INTV;        // in [0,255]
        const int   lb     = (int)floorf(pos);
        const int   hb     = min(lb + 1, NB - 1);
        const float wh     = pos - (float)lb;

        const float xlb = __ldg(base + (size_t)lb * HWSZ + j);
        const float xhb = __ldg(base + (size_t)hb * HWSZ + j);
        const float lse = __logf(ss[j]);
        const float ce  = lse - ((1.0f - wh) * xlb + wh * xhb);

        msum  += m;
        csum  += fabsf(cc[j] - target) * m;
        cesum += ce * m;
    }

    // ---- deterministic block reduction ----
    __shared__ float sh[3][THREADS1 / 32];
    const int lane = threadIdx.x & 31;
    const int wid  = threadIdx.x >> 5;

    msum  = warp_sum_f(msum);
    csum  = warp_sum_f(csum);
    cesum = warp_sum_f(cesum);
    if (lane == 0) { sh[0][wid] = msum; sh[1][wid] = csum; sh[2][wid] = cesum; }
    __syncthreads();

    __shared__ bool s_last;
    if (threadIdx.x == 0) {
        const int nw = THREADS1 / 32;
        float a = 0.f, bs = 0.f, c2 = 0.f;
        #pragma unroll
        for (int i = 0; i < nw; ++i) { a += sh[0][i]; bs += sh[1][i]; c2 += sh[2][i]; }
        g_part[blockIdx.x]        = a;
        g_part[1024 + blockIdx.x] = bs;
        g_part[2048 + blockIdx.x] = c2;
        __threadfence();
        const unsigned old = atomicInc(&g_count, NBLK1 - 1);  // wraps to 0 on last
        s_last = (old == NBLK1 - 1);
    }
    __syncthreads();

    // ---- last block: final reduction in double (fixed order => deterministic) ----
    if (s_last) {
        __threadfence();
        double a = 0.0, bs = 0.0, c2 = 0.0;
        for (int i = threadIdx.x; i < NBLK1; i += THREADS1) {
            a  += (double)__ldcg(&g_part[i]);
            bs += (double)__ldcg(&g_part[1024 + i]);
            c2 += (double)__ldcg(&g_part[2048 + i]);
        }
        __shared__ double dsh[3][THREADS1 / 32];
        a  = warp_sum_d(a);
        bs = warp_sum_d(bs);
        c2 = warp_sum_d(c2);
        if (lane == 0) { dsh[0][wid] = a; dsh[1][wid] = bs; dsh[2][wid] = c2; }
        __syncthreads();
        if (threadIdx.x == 0) {
            const int nw = THREADS1 / 32;
            double A = 0.0, Bs = 0.0, C = 0.0;
            #pragma unroll
            for (int i = 0; i < nw; ++i) { A += dsh[0][i]; Bs += dsh[1][i]; C += dsh[2][i]; }
            const double denom       = A + 1e-6;
            const double coord_loss  = Bs / denom;
            const double logits_loss = C / denom;
            out[0] = (float)(0.1 * coord_loss + logits_loss);
            if (out_size >= 3) {
                out[1] = (float)coord_loss;
                out[2] = (float)logits_loss;
            }
        }
    }
}

extern "C" void kernel_launch(void* const* d_in, const int* in_sizes, int n_in,
                              void* d_out, int out_size)
{
    const float* coord  = (const float*)d_in[0];
    const float* logits = (const float*)d_in[1];
    const float* disp   = (const float*)d_in[2];
    const int*   valid  = (const int*)d_in[3];
    float* out = (float*)d_out;

    disp_loss_fused<<<NBLK1, THREADS1>>>(coord, logits, disp, valid, out, out_size);
}